// round 1
// baseline (speedup 1.0000x reference)
#include <cuda_runtime.h>
#include <math.h>

#define NN   64
#define KK   32
#define FF   1024
#define OO   64      // C1*F1 = output width of W1
#define JJ   33      // x + 32 neighbors
#define C1c  4
#define F1c  16
#define C2c  32
#define NCLS 10
#define BN_EPS 1e-5f

// ---------------- scratch (device globals; no allocations) ----------------
__device__ float g_C[NN * JJ * FF];          // per node: C[j][a]  (8.65 MB)
__device__ float g_part[8 * NN * JJ * OO];   // split-K partials
__device__ float g_O1[NN * JJ * OO];         // W1 @ C  : [n][j][o]
__device__ float g_bn1[8];                   // mean[4], rstd[4]
__device__ float g_X2[NN * C2c];             // layer-2 pre-BN output

// ============================================================================
// K1: per-node build of C[a,j] = sum_b sign(x_a s_b + x_b s_a) * B[b,j]
//     via sort-by-r + prefix sums.  grid=64, block=1024.
// ============================================================================
__global__ void k_build(const float* __restrict__ x, const float* __restrict__ nb)
{
    int n = blockIdx.x;
    int t = threadIdx.x;               // 0..1023
    __shared__ float xs[FF];
    __shared__ float rr[FF];           // unsorted r
    __shared__ float rk[FF];           // sort keys
    __shared__ int   pm[FF];           // permutation payload
    __shared__ float gcol[FF];
    __shared__ float scn[FF];
    __shared__ int   ms[FF];
    __shared__ float wsum[32];

    const float* xrow   = x  + (size_t)n * FF;
    const float* nbbase = nb + (size_t)n * KK * FF;

    float xv = xrow[t];
    xs[t] = xv;
    float s = 0.f;
    #pragma unroll 8
    for (int k = 0; k < KK; k++) s += nbbase[k * FF + t];
    float r = s / xv;
    rr[t] = r;
    rk[t] = r;
    pm[t] = t;
    __syncthreads();

    // bitonic sort ascending on rk with payload pm
    for (int k = 2; k <= FF; k <<= 1) {
        for (int j = k >> 1; j > 0; j >>= 1) {
            int ixj = t ^ j;
            if (ixj > t) {
                bool up = ((t & k) == 0);
                float a = rk[t], b = rk[ixj];
                bool sw = up ? (a > b) : (a < b);
                if (sw) {
                    rk[t] = b; rk[ixj] = a;
                    int pa = pm[t]; pm[t] = pm[ixj]; pm[ixj] = pa;
                }
            }
            __syncthreads();
        }
    }

    // m*_a = count of sorted r strictly below -r_a
    {
        float th = -rr[t];
        int lo = 0, hi = FF;
        #pragma unroll
        for (int it = 0; it < 10; it++) {
            int mid = (lo + hi) >> 1;
            if (rk[mid] < th) lo = mid + 1; else hi = mid;
        }
        ms[t] = lo;
    }
    __syncthreads();

    int lane = t & 31, wid = t >> 5;
    float sgn_a = (xs[t] >= 0.f) ? 1.f : -1.f;
    float* Cout = g_C + (size_t)n * JJ * FF;

    for (int j = 0; j < JJ; j++) {
        float v = (j == 0) ? xs[t] : nbbase[(j - 1) * FF + t];
        gcol[t] = (xs[t] >= 0.f) ? v : -v;          // sign(x_b) * B[b,j]
        __syncthreads();

        float val = gcol[pm[t]];                     // gather into sorted order
        // warp inclusive scan
        #pragma unroll
        for (int d = 1; d < 32; d <<= 1) {
            float o = __shfl_up_sync(0xffffffffu, val, d);
            if (lane >= d) val += o;
        }
        if (lane == 31) wsum[wid] = val;
        __syncthreads();
        if (wid == 0) {
            float wv = wsum[lane];
            #pragma unroll
            for (int d = 1; d < 32; d <<= 1) {
                float o = __shfl_up_sync(0xffffffffu, wv, d);
                if (lane >= d) wv += o;
            }
            wsum[lane] = wv;                         // inclusive over warps
        }
        __syncthreads();
        float off = (wid == 0) ? 0.f : wsum[wid - 1];
        scn[t] = val + off;                          // inclusive prefix at sorted pos t
        __syncthreads();

        float T = scn[FF - 1];
        int   m = ms[t];
        float P = (m == 0) ? 0.f : scn[m - 1];
        Cout[j * FF + t] = sgn_a * (T - 2.f * P);
        __syncthreads();                             // protect gcol/scn/wsum for next j
    }
}

// ============================================================================
// K2: GEMM  out1[m][o] = sum_a C[m][a] * W1[o][a],  M=2112, N=64, K=1024
//     split-K by 8; grid=(33,8), block=256, tile 64Mx64N per CTA.
// ============================================================================
__global__ void k_gemm(const float* __restrict__ W1)
{
    __shared__ float Cs[64][33];
    __shared__ float Ws[64][33];
    int mt  = blockIdx.x;          // 0..32
    int ks  = blockIdx.y;          // 0..7
    int tid = threadIdx.x;         // 0..255
    int mg  = tid >> 4;            // 0..15  -> m = mg*4 + i
    int og  = tid & 15;            // 0..15  -> o = og*4 + ii

    float acc[4][4];
    #pragma unroll
    for (int i = 0; i < 4; i++)
        #pragma unroll
        for (int ii = 0; ii < 4; ii++) acc[i][ii] = 0.f;

    int kb0 = ks * (FF / 8);
    for (int kb = kb0; kb < kb0 + (FF / 8); kb += 32) {
        // stage tiles
        #pragma unroll
        for (int u = 0; u < 8; u++) {
            int e  = tid * 8 + u;
            int ri = e >> 5, kc = e & 31;
            Cs[ri][kc] = g_C[(size_t)(mt * 64 + ri) * FF + kb + kc];
            Ws[ri][kc] = W1 [(size_t)ri * FF + kb + kc];
        }
        __syncthreads();
        #pragma unroll
        for (int kc = 0; kc < 32; kc++) {
            float ca[4], wb[4];
            #pragma unroll
            for (int i = 0; i < 4; i++)  ca[i] = Cs[mg * 4 + i][kc];
            #pragma unroll
            for (int ii = 0; ii < 4; ii++) wb[ii] = Ws[og * 4 + ii][kc];
            #pragma unroll
            for (int i = 0; i < 4; i++)
                #pragma unroll
                for (int ii = 0; ii < 4; ii++)
                    acc[i][ii] += ca[i] * wb[ii];
        }
        __syncthreads();
    }
    float* pbase = g_part + (size_t)ks * (NN * JJ * OO);
    #pragma unroll
    for (int i = 0; i < 4; i++) {
        int m = mt * 64 + mg * 4 + i;
        #pragma unroll
        for (int ii = 0; ii < 4; ii++)
            pbase[(size_t)m * OO + og * 4 + ii] = acc[i][ii];
    }
}

// reduce split-K partials
__global__ void k_red()
{
    int idx = blockIdx.x * 256 + threadIdx.x;   // grid 528*256 = 135168 exact
    float a = 0.f;
    #pragma unroll
    for (int ks = 0; ks < 8; ks++) a += g_part[(size_t)ks * (NN * JJ * OO) + idx];
    g_O1[idx] = a;
}

// BN1 stats over x-path: mean/var per channel c over (n, f)
__global__ void k_bn1stats()
{
    __shared__ float r1[256], r2[256];
    int t = threadIdx.x;          // 256 = 4c x 64n
    int c = t >> 6, i = t & 63;
    float s1 = 0.f, s2 = 0.f;
    #pragma unroll
    for (int f = 0; f < F1c; f++) {
        float v = g_O1[(size_t)(i * JJ) * OO + c * F1c + f];
        s1 += v; s2 += v * v;
    }
    r1[t] = s1; r2[t] = s2;
    __syncthreads();
    for (int st = 32; st > 0; st >>= 1) {
        if (i < st) { r1[t] += r1[t + st]; r2[t] += r2[t + st]; }
        __syncthreads();
    }
    if (i == 0) {
        float m  = r1[t] / 1024.f;
        float var = r2[t] / 1024.f - m * m;
        g_bn1[c]     = m;
        g_bn1[4 + c] = rsqrtf(var + BN_EPS);
    }
}

// ============================================================================
// K3: per-node layer 2.  grid=64, block=128.
// ============================================================================
__global__ void k_layer2(const float* __restrict__ W2,
                         const float* __restrict__ bn1w, const float* __restrict__ bn1b)
{
    int n = blockIdx.x, t = threadIdx.x;      // 128 threads
    __shared__ float x1s[64];
    __shared__ float nbraw[KK * 64];
    __shared__ float nb1s[KK * 64];
    __shared__ float t2s[64];
    __shared__ float xa2s[64];
    __shared__ float cm[4], cr[4];

    if (t < 64) {
        float v = g_O1[(size_t)(n * JJ) * OO + t];
        int c = t >> 4;
        float y = (v - g_bn1[c]) * g_bn1[4 + c] * bn1w[c] + bn1b[c];
        x1s[t] = y / (1.f + fabsf(y));
    }
    for (int i = t; i < KK * 64; i += 128)
        nbraw[i] = g_O1[(size_t)(n * JJ + 1 + (i >> 6)) * OO + (i & 63)];
    __syncthreads();

    // per-channel stats over (k,f): warp c
    int wid = t >> 5, lane = t & 31;
    {
        int c = wid;
        float s1 = 0.f, s2 = 0.f;
        #pragma unroll
        for (int m = 0; m < 16; m++) {
            int i = lane + 32 * m;            // 0..511
            int k = i >> 4, f = i & 15;
            float v = nbraw[k * 64 + c * 16 + f];
            s1 += v; s2 += v * v;
        }
        #pragma unroll
        for (int d = 16; d > 0; d >>= 1) {
            s1 += __shfl_down_sync(0xffffffffu, s1, d);
            s2 += __shfl_down_sync(0xffffffffu, s2, d);
        }
        if (lane == 0) {
            float m1 = s1 / 512.f;
            float var = s2 / 512.f - m1 * m1;
            cm[c] = m1; cr[c] = rsqrtf(var + BN_EPS);
        }
    }
    __syncthreads();
    for (int i = t; i < KK * 64; i += 128) {
        int c = (i >> 4) & 3;
        float y = (nbraw[i] - cm[c]) * cr[c] * bn1w[c] + bn1b[c];
        nb1s[i] = y / (1.f + fabsf(y));
    }
    __syncthreads();
    if (t < 64) {
        float a = 0.f;
        #pragma unroll 8
        for (int k = 0; k < KK; k++) a += nb1s[k * 64 + t];
        t2s[t] = a;
    }
    __syncthreads();
    if (t < 64) {
        int c = t >> 4, ai = t & 15;
        float acc = 0.f;
        for (int b = 0; b < 16; b++) {
            float den = 1e-7f, sgc = 0.f;
            #pragma unroll
            for (int cc = 0; cc < 4; cc++) {
                float raw = x1s[cc * 16 + ai] * t2s[cc * 16 + b]
                          + x1s[cc * 16 + b]  * t2s[cc * 16 + ai];
                float mag = sqrtf(fmaxf(fabsf(raw), 1e-8f));
                float sg  = (raw > 0.f) ? mag : ((raw < 0.f) ? -mag : 0.f);
                den += fabsf(sg);
                if (cc == c) sgc = sg;
            }
            acc += (sgc / den) * x1s[c * 16 + b];
        }
        xa2s[t] = acc;
    }
    __syncthreads();
    if (t < C2c) {
        float acc = 0.f;
        #pragma unroll
        for (int i = 0; i < 64; i++) acc += W2[t * 64 + i] * xa2s[i];
        g_X2[n * C2c + t] = acc;
    }
}

// ============================================================================
// K4: BN2 (over nodes) + softsign + linear.  1 CTA, 640 threads.
// ============================================================================
__global__ void k_final(const float* __restrict__ bn2w, const float* __restrict__ bn2b,
                        const float* __restrict__ lw,  const float* __restrict__ lb,
                        float* __restrict__ out)
{
    int t = threadIdx.x;
    __shared__ float z[NN * C2c];
    __shared__ float qm[C2c], qr[C2c];
    if (t < C2c) {
        float s1 = 0.f, s2 = 0.f;
        #pragma unroll 8
        for (int nn = 0; nn < NN; nn++) {
            float v = g_X2[nn * C2c + t];
            s1 += v; s2 += v * v;
        }
        float m  = s1 / 64.f;
        float var = s2 / 64.f - m * m;
        qm[t] = m; qr[t] = rsqrtf(var + BN_EPS);
    }
    __syncthreads();
    for (int i = t; i < NN * C2c; i += 640) {
        int q = i & 31;
        float y = (g_X2[i] - qm[q]) * qr[q] * bn2w[q] + bn2b[q];
        z[i] = y / (1.f + fabsf(y));
    }
    __syncthreads();
    if (t < NN * NCLS) {
        int nn = t / NCLS, cls = t - nn * NCLS;
        float acc = lb[cls];
        #pragma unroll
        for (int q = 0; q < C2c; q++) acc += z[nn * C2c + q] * lw[cls * C2c + q];
        out[t] = acc;
    }
}

// ============================================================================
extern "C" void kernel_launch(void* const* d_in, const int* in_sizes, int n_in,
                              void* d_out, int out_size)
{
    const float* x    = (const float*)d_in[0];
    const float* nb   = (const float*)d_in[1];
    const float* W1   = (const float*)d_in[2];
    const float* W2   = (const float*)d_in[3];
    const float* bn1w = (const float*)d_in[4];
    const float* bn1b = (const float*)d_in[5];
    const float* bn2w = (const float*)d_in[6];
    const float* bn2b = (const float*)d_in[7];
    const float* lw   = (const float*)d_in[8];
    const float* lb   = (const float*)d_in[9];
    float* out = (float*)d_out;

    k_build<<<NN, 1024>>>(x, nb);
    dim3 gg(33, 8);
    k_gemm<<<gg, 256>>>(W1);
    k_red<<<528, 256>>>();
    k_bn1stats<<<1, 256>>>();
    k_layer2<<<NN, 128>>>(W2, bn1w, bn1b);
    k_final<<<1, 640>>>(bn2w, bn2b, lw, lb, out);
}

// round 2
// speedup vs baseline: 1.2529x; 1.2529x over previous
#include <cuda_runtime.h>
#include <math.h>

#define NN   64
#define KK   32
#define FF   1024
#define OO   64      // C1*F1
#define JJ   33
#define C1c  4
#define F1c  16
#define C2c  32
#define NCLS 10
#define BN_EPS 1e-5f

// ---------------- scratch (device globals; no allocations) ----------------
__device__ float g_C[NN * JJ * FF];          // per node: C[j][a]
__device__ float g_part[8 * NN * JJ * OO];   // split-K partials
__device__ float g_O1[NN * JJ * OO];         // W1 @ C
__device__ float g_X2[NN * C2c];
__device__ int   g_ipm[NN * FF];             // inverse permutation (orig -> sorted pos)
__device__ int   g_ms[NN * FF];              // threshold rank per a
__device__ float g_sgn[NN * FF];             // sign(x_b)
__device__ int   g_cnt[64];                  // gemm last-block counters (33 used)

// ============================================================================
// K1: per-node sort of r = s/x. Hybrid bitonic: intra-warp passes in registers
// via shfl_xor (no barriers), cross-warp passes via shared. grid=64, block=1024.
// ============================================================================
__global__ void k_sort(const float* __restrict__ x, const float* __restrict__ nb)
{
    int n = blockIdx.x, t = threadIdx.x;
    __shared__ float sk[FF];
    __shared__ int   sp[FF];

    if (n == 0 && t < 64) g_cnt[t] = 0;      // reset gemm counters each replay

    float xv = x[(size_t)n * FF + t];
    const float* nbb = nb + (size_t)n * KK * FF;
    float s = 0.f;
    #pragma unroll
    for (int k = 0; k < KK; k++) s += nbb[k * FF + t];

    float key = s / xv;                       // r_b
    int   pay = t;
    float myr = key;                          // threshold source (own r)
    g_sgn[(size_t)n * FF + t] = (xv >= 0.f) ? 1.f : -1.f;

    // intra-warp stages k = 2..32 (strides <= 16: all shuffle, no barriers)
    #pragma unroll
    for (int k = 2; k <= 32; k <<= 1) {
        #pragma unroll
        for (int j = k >> 1; j >= 1; j >>= 1) {
            float ok = __shfl_xor_sync(0xffffffffu, key, j);
            int   op = __shfl_xor_sync(0xffffffffu, pay, j);
            bool keepmin = (((t & k) == 0) == ((t & j) == 0));
            bool take = keepmin ? (ok < key) : (ok > key);
            if (take) { key = ok; pay = op; }
        }
    }
    // stages k = 64..1024: cross-warp passes via shared, tails via shuffle
    for (int k = 64; k <= FF; k <<= 1) {
        for (int j = k >> 1; j >= 32; j >>= 1) {
            sk[t] = key; sp[t] = pay;
            __syncthreads();
            float ok = sk[t ^ j]; int op = sp[t ^ j];
            bool keepmin = (((t & k) == 0) == ((t & j) == 0));
            bool take = keepmin ? (ok < key) : (ok > key);
            if (take) { key = ok; pay = op; }
            __syncthreads();
        }
        #pragma unroll
        for (int j = 16; j >= 1; j >>= 1) {
            float ok = __shfl_xor_sync(0xffffffffu, key, j);
            int   op = __shfl_xor_sync(0xffffffffu, pay, j);
            bool keepmin = (((t & k) == 0) == ((t & j) == 0));
            bool take = keepmin ? (ok < key) : (ok > key);
            if (take) { key = ok; pay = op; }
        }
    }

    sk[t] = key;                              // sorted keys for binary search
    g_ipm[(size_t)n * FF + pay] = t;          // inverse permutation
    __syncthreads();

    // m*_a = count of sorted r strictly below -r_a
    float th = -myr;
    int lo = 0, hi = FF;
    #pragma unroll
    for (int it = 0; it < 10; it++) {
        int mid = (lo + hi) >> 1;
        if (sk[mid] < th) lo = mid + 1; else hi = mid;
    }
    g_ms[(size_t)n * FF + t] = lo;
}

// ============================================================================
// K2: per-(n,j) column scan + threshold lookup. grid=(33,64), block=1024.
// ============================================================================
__global__ void k_cols(const float* __restrict__ x, const float* __restrict__ nb)
{
    int j = blockIdx.x, n = blockIdx.y, t = threadIdx.x;
    __shared__ float sc[FF];
    __shared__ float ws[32];

    const float* col = (j == 0) ? (x + (size_t)n * FF)
                                : (nb + ((size_t)n * KK + (j - 1)) * FF);
    float sg = g_sgn[(size_t)n * FF + t];
    float v  = col[t] * sg;                   // sign(x_b) * B[b,j]
    sc[g_ipm[(size_t)n * FF + t]] = v;        // scatter into sorted order
    __syncthreads();

    float val = sc[t];
    int lane = t & 31, wid = t >> 5;
    #pragma unroll
    for (int d = 1; d < 32; d <<= 1) {
        float o = __shfl_up_sync(0xffffffffu, val, d);
        if (lane >= d) val += o;
    }
    if (lane == 31) ws[wid] = val;
    __syncthreads();
    if (wid == 0) {
        float wv = ws[lane];
        #pragma unroll
        for (int d = 1; d < 32; d <<= 1) {
            float o = __shfl_up_sync(0xffffffffu, wv, d);
            if (lane >= d) wv += o;
        }
        ws[lane] = wv;
    }
    __syncthreads();
    float off = wid ? ws[wid - 1] : 0.f;
    sc[t] = val + off;                        // inclusive prefix at sorted pos t
    __syncthreads();

    float T = sc[FF - 1];
    int   m = g_ms[(size_t)n * FF + t];
    float P = m ? sc[m - 1] : 0.f;
    g_C[((size_t)n * JJ + j) * FF + t] = sg * (T - 2.f * P);
}

// ============================================================================
// K3: GEMM out1[m][o] = sum_a C[m][a] W1[o][a], M=2112 N=64 K=1024, split-K 8,
// fused deterministic last-CTA reduction. grid=(33,8), block=256.
// ============================================================================
__global__ void k_gemm(const float* __restrict__ W1)
{
    __shared__ float Cs[64][33];
    __shared__ float Ws[64][33];
    __shared__ int last;
    int mt  = blockIdx.x;
    int ks  = blockIdx.y;
    int tid = threadIdx.x;
    int mg  = tid >> 4;
    int og  = tid & 15;

    float acc[4][4];
    #pragma unroll
    for (int i = 0; i < 4; i++)
        #pragma unroll
        for (int ii = 0; ii < 4; ii++) acc[i][ii] = 0.f;

    int kb0 = ks * (FF / 8);
    for (int kb = kb0; kb < kb0 + (FF / 8); kb += 32) {
        #pragma unroll
        for (int u = 0; u < 8; u++) {
            int e  = u * 256 + tid;           // fully coalesced
            int ri = e >> 5, kc = e & 31;
            Cs[ri][kc] = g_C[(size_t)(mt * 64 + ri) * FF + kb + kc];
            Ws[ri][kc] = W1 [(size_t)ri * FF + kb + kc];
        }
        __syncthreads();
        #pragma unroll
        for (int kc = 0; kc < 32; kc++) {
            float ca[4], wb[4];
            #pragma unroll
            for (int i = 0; i < 4; i++)  ca[i] = Cs[mg * 4 + i][kc];
            #pragma unroll
            for (int ii = 0; ii < 4; ii++) wb[ii] = Ws[og * 4 + ii][kc];
            #pragma unroll
            for (int i = 0; i < 4; i++)
                #pragma unroll
                for (int ii = 0; ii < 4; ii++)
                    acc[i][ii] += ca[i] * wb[ii];
        }
        __syncthreads();
    }
    float* pb = g_part + (size_t)ks * (NN * JJ * OO) + (size_t)mt * 64 * OO;
    #pragma unroll
    for (int i = 0; i < 4; i++)
        #pragma unroll
        for (int ii = 0; ii < 4; ii++)
            pb[(mg * 4 + i) * OO + og * 4 + ii] = acc[i][ii];

    __threadfence();
    __syncthreads();
    if (tid == 0) last = (atomicAdd(&g_cnt[mt], 1) == 7);
    __syncthreads();
    if (last) {
        __threadfence();
        const float4* ps = (const float4*)g_part;
        float4* po = (float4*)g_O1;
        for (int i = tid; i < 1024; i += 256) {
            float4 a = make_float4(0.f, 0.f, 0.f, 0.f);
            #pragma unroll
            for (int s = 0; s < 8; s++) {
                float4 p = ps[(size_t)s * (NN * JJ * OO / 4) + mt * 1024 + i];
                a.x += p.x; a.y += p.y; a.z += p.z; a.w += p.w;
            }
            po[mt * 1024 + i] = a;
        }
    }
}

// ============================================================================
// K4: per-node layer 2 with fused (redundant) BN1 x-path stats. grid=64, block=128.
// ============================================================================
__global__ void k_layer2(const float* __restrict__ W2,
                         const float* __restrict__ bn1w, const float* __restrict__ bn1b)
{
    int n = blockIdx.x, t = threadIdx.x;
    __shared__ float x1s[64];
    __shared__ float nbraw[KK * 64];
    __shared__ float nb1s[KK * 64];
    __shared__ float t2s[64];
    __shared__ float xa2s[64];
    __shared__ float cm[4], cr[4];           // nb-path stats
    __shared__ float gm[4], gr[4];           // x-path (global) stats

    int wid = t >> 5, lane = t & 31;

    // --- BN1 x-path stats over all nodes (redundant per CTA, L2-hot) ---
    {
        int c = wid;                          // 4 warps = 4 channels
        float s1 = 0.f, s2 = 0.f;
        #pragma unroll
        for (int q = 0; q < 32; q++) {
            int idx = lane * 32 + q;          // 0..1023 within channel
            int np = idx >> 4, f = idx & 15;
            float v = g_O1[(size_t)(np * JJ) * OO + c * F1c + f];
            s1 += v; s2 += v * v;
        }
        #pragma unroll
        for (int d = 16; d > 0; d >>= 1) {
            s1 += __shfl_down_sync(0xffffffffu, s1, d);
            s2 += __shfl_down_sync(0xffffffffu, s2, d);
        }
        if (lane == 0) {
            float m = s1 / 1024.f;
            gm[c] = m;
            gr[c] = rsqrtf(s2 / 1024.f - m * m + BN_EPS);
        }
    }

    for (int i = t; i < KK * 64; i += 128)
        nbraw[i] = g_O1[(size_t)(n * JJ + 1 + (i >> 6)) * OO + (i & 63)];
    __syncthreads();

    if (t < 64) {
        float v = g_O1[(size_t)(n * JJ) * OO + t];
        int c = t >> 4;
        float y = (v - gm[c]) * gr[c] * bn1w[c] + bn1b[c];
        x1s[t] = y / (1.f + fabsf(y));
    }

    // per-channel stats of this node's neighbor set over (k,f)
    {
        int c = wid;
        float s1 = 0.f, s2 = 0.f;
        #pragma unroll
        for (int m = 0; m < 16; m++) {
            int i = lane + 32 * m;
            int k = i >> 4, f = i & 15;
            float v = nbraw[k * 64 + c * 16 + f];
            s1 += v; s2 += v * v;
        }
        #pragma unroll
        for (int d = 16; d > 0; d >>= 1) {
            s1 += __shfl_down_sync(0xffffffffu, s1, d);
            s2 += __shfl_down_sync(0xffffffffu, s2, d);
        }
        if (lane == 0) {
            float m1 = s1 / 512.f;
            cm[c] = m1; cr[c] = rsqrtf(s2 / 512.f - m1 * m1 + BN_EPS);
        }
    }
    __syncthreads();
    for (int i = t; i < KK * 64; i += 128) {
        int c = (i >> 4) & 3;
        float y = (nbraw[i] - cm[c]) * cr[c] * bn1w[c] + bn1b[c];
        nb1s[i] = y / (1.f + fabsf(y));
    }
    __syncthreads();
    if (t < 64) {
        float a = 0.f;
        #pragma unroll 8
        for (int k = 0; k < KK; k++) a += nb1s[k * 64 + t];
        t2s[t] = a;
    }
    __syncthreads();
    if (t < 64) {
        int c = t >> 4, ai = t & 15;
        float acc = 0.f;
        for (int b = 0; b < 16; b++) {
            float den = 1e-7f, sgc = 0.f;
            #pragma unroll
            for (int cc = 0; cc < 4; cc++) {
                float raw = x1s[cc * 16 + ai] * t2s[cc * 16 + b]
                          + x1s[cc * 16 + b]  * t2s[cc * 16 + ai];
                float mag = sqrtf(fmaxf(fabsf(raw), 1e-8f));
                float sg  = (raw > 0.f) ? mag : ((raw < 0.f) ? -mag : 0.f);
                den += fabsf(sg);
                if (cc == c) sgc = sg;
            }
            acc += (sgc / den) * x1s[c * 16 + b];
        }
        xa2s[t] = acc;
    }
    __syncthreads();
    if (t < C2c) {
        float acc = 0.f;
        #pragma unroll
        for (int i = 0; i < 64; i++) acc += W2[t * 64 + i] * xa2s[i];
        g_X2[n * C2c + t] = acc;
    }
}

// ============================================================================
// K5: BN2 + softsign + linear. 1 CTA, 640 threads.
// ============================================================================
__global__ void k_final(const float* __restrict__ bn2w, const float* __restrict__ bn2b,
                        const float* __restrict__ lw,  const float* __restrict__ lb,
                        float* __restrict__ out)
{
    int t = threadIdx.x;
    __shared__ float z[NN * C2c];
    __shared__ float qm[C2c], qr[C2c];
    if (t < C2c) {
        float s1 = 0.f, s2 = 0.f;
        #pragma unroll 8
        for (int nn = 0; nn < NN; nn++) {
            float v = g_X2[nn * C2c + t];
            s1 += v; s2 += v * v;
        }
        float m = s1 / 64.f;
        qm[t] = m; qr[t] = rsqrtf(s2 / 64.f - m * m + BN_EPS);
    }
    __syncthreads();
    for (int i = t; i < NN * C2c; i += 640) {
        int q = i & 31;
        float y = (g_X2[i] - qm[q]) * qr[q] * bn2w[q] + bn2b[q];
        z[i] = y / (1.f + fabsf(y));
    }
    __syncthreads();
    if (t < NN * NCLS) {
        int nn = t / NCLS, cls = t - nn * NCLS;
        float acc = lb[cls];
        #pragma unroll
        for (int q = 0; q < C2c; q++) acc += z[nn * C2c + q] * lw[cls * C2c + q];
        out[t] = acc;
    }
}

// ============================================================================
extern "C" void kernel_launch(void* const* d_in, const int* in_sizes, int n_in,
                              void* d_out, int out_size)
{
    const float* x    = (const float*)d_in[0];
    const float* nb   = (const float*)d_in[1];
    const float* W1   = (const float*)d_in[2];
    const float* W2   = (const float*)d_in[3];
    const float* bn1w = (const float*)d_in[4];
    const float* bn1b = (const float*)d_in[5];
    const float* bn2w = (const float*)d_in[6];
    const float* bn2b = (const float*)d_in[7];
    const float* lw   = (const float*)d_in[8];
    const float* lb   = (const float*)d_in[9];
    float* out = (float*)d_out;

    k_sort<<<NN, 1024>>>(x, nb);
    dim3 gc(JJ, NN);
    k_cols<<<gc, 1024>>>(x, nb);
    dim3 gg(33, 8);
    k_gemm<<<gg, 256>>>(W1);
    k_layer2<<<NN, 128>>>(W2, bn1w, bn1b);
    k_final<<<1, 640>>>(bn2w, bn2b, lw, lb, out);
}

// round 3
// speedup vs baseline: 1.4496x; 1.1570x over previous
#include <cuda_runtime.h>
#include <math.h>

#define NN   64
#define KK   32
#define FF   1024
#define OO   64      // C1*F1
#define JJ   33
#define C1c  4
#define F1c  16
#define C2c  32
#define NCLS 10
#define BN_EPS 1e-5f

// ---------------- scratch (device globals; no allocations) ----------------
__device__ float g_C[NN * JJ * FF];          // per node: C[j][a]
__device__ float g_part[8 * NN * JJ * OO];   // split-K partials
__device__ float g_O1[NN * JJ * OO];         // W1 @ C
__device__ float g_X2[NN * C2c];
__device__ int   g_ipm[NN * FF];             // inverse permutation
__device__ int   g_ms[NN * FF];              // threshold rank per a
__device__ float g_sgn[NN * FF];             // sign(x_b)
__device__ int   g_cnt[64];                  // gemm last-block counters
__device__ int   g_cnt2[1];                  // layer2 last-block counter

// ============================================================================
// K1: per-node hybrid bitonic sort of r = s/x. grid=64, block=1024.
// ============================================================================
__global__ void k_sort(const float* __restrict__ x, const float* __restrict__ nb)
{
    int n = blockIdx.x, t = threadIdx.x;
    __shared__ float sk[FF];
    __shared__ int   sp[FF];

    if (n == 0 && t < 64) g_cnt[t] = 0;
    if (n == 0 && t == 64) g_cnt2[0] = 0;

    float xv = x[(size_t)n * FF + t];
    const float* nbb = nb + (size_t)n * KK * FF;
    float s = 0.f;
    #pragma unroll
    for (int k = 0; k < KK; k++) s += nbb[k * FF + t];

    float key = s / xv;
    int   pay = t;
    float myr = key;
    g_sgn[(size_t)n * FF + t] = (xv >= 0.f) ? 1.f : -1.f;

    #pragma unroll
    for (int k = 2; k <= 32; k <<= 1) {
        #pragma unroll
        for (int j = k >> 1; j >= 1; j >>= 1) {
            float ok = __shfl_xor_sync(0xffffffffu, key, j);
            int   op = __shfl_xor_sync(0xffffffffu, pay, j);
            bool keepmin = (((t & k) == 0) == ((t & j) == 0));
            bool take = keepmin ? (ok < key) : (ok > key);
            if (take) { key = ok; pay = op; }
        }
    }
    for (int k = 64; k <= FF; k <<= 1) {
        for (int j = k >> 1; j >= 32; j >>= 1) {
            sk[t] = key; sp[t] = pay;
            __syncthreads();
            float ok = sk[t ^ j]; int op = sp[t ^ j];
            bool keepmin = (((t & k) == 0) == ((t & j) == 0));
            bool take = keepmin ? (ok < key) : (ok > key);
            if (take) { key = ok; pay = op; }
            __syncthreads();
        }
        #pragma unroll
        for (int j = 16; j >= 1; j >>= 1) {
            float ok = __shfl_xor_sync(0xffffffffu, key, j);
            int   op = __shfl_xor_sync(0xffffffffu, pay, j);
            bool keepmin = (((t & k) == 0) == ((t & j) == 0));
            bool take = keepmin ? (ok < key) : (ok > key);
            if (take) { key = ok; pay = op; }
        }
    }

    sk[t] = key;
    g_ipm[(size_t)n * FF + pay] = t;
    __syncthreads();

    float th = -myr;
    int lo = 0, hi = FF;
    #pragma unroll
    for (int it = 0; it < 10; it++) {
        int mid = (lo + hi) >> 1;
        if (sk[mid] < th) lo = mid + 1; else hi = mid;
    }
    g_ms[(size_t)n * FF + t] = lo;
}

// ============================================================================
// K2: per-(n,j) column scan + threshold lookup. grid=(33,64), block=1024.
// ============================================================================
__global__ void k_cols(const float* __restrict__ x, const float* __restrict__ nb)
{
    int j = blockIdx.x, n = blockIdx.y, t = threadIdx.x;
    __shared__ float sc[FF];
    __shared__ float ws[32];

    const float* col = (j == 0) ? (x + (size_t)n * FF)
                                : (nb + ((size_t)n * KK + (j - 1)) * FF);
    int   ip = g_ipm[(size_t)n * FF + t];
    int   m  = g_ms[(size_t)n * FF + t];
    float sg = g_sgn[(size_t)n * FF + t];
    float v  = col[t] * sg;
    sc[ip] = v;
    __syncthreads();

    float val = sc[t];
    int lane = t & 31, wid = t >> 5;
    #pragma unroll
    for (int d = 1; d < 32; d <<= 1) {
        float o = __shfl_up_sync(0xffffffffu, val, d);
        if (lane >= d) val += o;
    }
    if (lane == 31) ws[wid] = val;
    __syncthreads();
    if (wid == 0) {
        float wv = ws[lane];
        #pragma unroll
        for (int d = 1; d < 32; d <<= 1) {
            float o = __shfl_up_sync(0xffffffffu, wv, d);
            if (lane >= d) wv += o;
        }
        ws[lane] = wv;
    }
    __syncthreads();
    float off = wid ? ws[wid - 1] : 0.f;
    sc[t] = val + off;
    __syncthreads();

    float T = sc[FF - 1];
    float P = m ? sc[m - 1] : 0.f;
    g_C[((size_t)n * JJ + j) * FF + t] = sg * (T - 2.f * P);
}

// ============================================================================
// K3: GEMM + fused deterministic split-K reduce. grid=(33,8), block=256.
// ============================================================================
__global__ void k_gemm(const float* __restrict__ W1)
{
    __shared__ float Cs[64][33];
    __shared__ float Ws[64][33];
    __shared__ int last;
    int mt  = blockIdx.x;
    int ks  = blockIdx.y;
    int tid = threadIdx.x;
    int mg  = tid >> 4;
    int og  = tid & 15;

    float acc[4][4];
    #pragma unroll
    for (int i = 0; i < 4; i++)
        #pragma unroll
        for (int ii = 0; ii < 4; ii++) acc[i][ii] = 0.f;

    int kb0 = ks * (FF / 8);
    for (int kb = kb0; kb < kb0 + (FF / 8); kb += 32) {
        #pragma unroll
        for (int u = 0; u < 8; u++) {
            int e  = u * 256 + tid;
            int ri = e >> 5, kc = e & 31;
            Cs[ri][kc] = g_C[(size_t)(mt * 64 + ri) * FF + kb + kc];
            Ws[ri][kc] = W1 [(size_t)ri * FF + kb + kc];
        }
        __syncthreads();
        #pragma unroll
        for (int kc = 0; kc < 32; kc++) {
            float ca[4], wb[4];
            #pragma unroll
            for (int i = 0; i < 4; i++)  ca[i] = Cs[mg * 4 + i][kc];
            #pragma unroll
            for (int ii = 0; ii < 4; ii++) wb[ii] = Ws[og * 4 + ii][kc];
            #pragma unroll
            for (int i = 0; i < 4; i++)
                #pragma unroll
                for (int ii = 0; ii < 4; ii++)
                    acc[i][ii] += ca[i] * wb[ii];
        }
        __syncthreads();
    }
    float* pb = g_part + (size_t)ks * (NN * JJ * OO) + (size_t)mt * 64 * OO;
    #pragma unroll
    for (int i = 0; i < 4; i++)
        #pragma unroll
        for (int ii = 0; ii < 4; ii++)
            pb[(mg * 4 + i) * OO + og * 4 + ii] = acc[i][ii];

    __threadfence();
    __syncthreads();
    if (tid == 0) last = (atomicAdd(&g_cnt[mt], 1) == 7);
    __syncthreads();
    if (last) {
        __threadfence();
        const float4* ps = (const float4*)g_part;
        float4* po = (float4*)g_O1;
        for (int i = tid; i < 1024; i += 256) {
            float4 a = make_float4(0.f, 0.f, 0.f, 0.f);
            #pragma unroll
            for (int s = 0; s < 8; s++) {
                float4 p = ps[(size_t)s * (NN * JJ * OO / 4) + mt * 1024 + i];
                a.x += p.x; a.y += p.y; a.z += p.z; a.w += p.w;
            }
            po[mt * 1024 + i] = a;
        }
    }
}

// ============================================================================
// K4: layer2 (parallelized) + fused BN2/linear in last CTA. grid=64, block=256.
// ============================================================================
__global__ void k_layer2(const float* __restrict__ W2,
                         const float* __restrict__ bn1w, const float* __restrict__ bn1b,
                         const float* __restrict__ bn2w, const float* __restrict__ bn2b,
                         const float* __restrict__ lw,  const float* __restrict__ lb,
                         float* __restrict__ out)
{
    int n = blockIdx.x, t = threadIdx.x;      // 256 threads
    __shared__ float nbs[KK * 64];            // neighbor buffer (reused as z later)
    __shared__ float red[4 * 256];
    __shared__ float x1s[64], t2s[64], xa2s[64];
    __shared__ float gm[4], gr[4], cm[4], cr[4];
    __shared__ int last;

    // --- coalesced loads ---
    for (int i = t; i < KK * 64; i += 256)
        nbs[i] = g_O1[(size_t)(n * JJ + 1 + (i >> 6)) * OO + (i & 63)];

    // global x-path stats: thread owns fixed feature column f6 (coalesced rows)
    int f6 = t & 63, c4 = (t >> 4) & 3;
    float gs1 = 0.f, gs2 = 0.f;
    for (int row = (t >> 6); row < NN; row += 4) {
        float v = g_O1[(size_t)row * JJ * OO + f6];
        gs1 += v; gs2 += v * v;
    }
    __syncthreads();                          // nbs ready

    // per-node nb stats, same (channel, member) mapping
    float ns1 = 0.f, ns2 = 0.f;
    {
        int f = t & 15, kg = t >> 6;
        #pragma unroll
        for (int k = kg * 8; k < kg * 8 + 8; k++) {
            float v = nbs[k * 64 + c4 * 16 + f];
            ns1 += v; ns2 += v * v;
        }
    }
    int slot = c4 * 64 + ((t >> 6) * 16 + (t & 15));   // bijection over 256
    red[slot] = gs1; red[256 + slot] = gs2;
    red[512 + slot] = ns1; red[768 + slot] = ns2;
    __syncthreads();
    #pragma unroll
    for (int st = 32; st > 0; st >>= 1) {
        if ((slot & 63) < st) {
            red[slot]       += red[slot + st];
            red[256 + slot] += red[256 + slot + st];
            red[512 + slot] += red[512 + slot + st];
            red[768 + slot] += red[768 + slot + st];
        }
        __syncthreads();
    }
    if (t < 4) {
        float m = red[t * 64] / 1024.f;
        gm[t] = m; gr[t] = rsqrtf(red[256 + t * 64] / 1024.f - m * m + BN_EPS);
        float m2 = red[512 + t * 64] / 512.f;
        cm[t] = m2; cr[t] = rsqrtf(red[768 + t * 64] / 512.f - m2 * m2 + BN_EPS);
    }
    __syncthreads();

    if (t < 64) {
        float v = g_O1[(size_t)(n * JJ) * OO + t];
        int c = t >> 4;
        float y = (v - gm[c]) * gr[c] * bn1w[c] + bn1b[c];
        x1s[t] = y / (1.f + fabsf(y));
    }
    for (int i = t; i < KK * 64; i += 256) {
        int c = (i >> 4) & 3;
        float y = (nbs[i] - cm[c]) * cr[c] * bn1w[c] + bn1b[c];
        nbs[i] = y / (1.f + fabsf(y));
    }
    __syncthreads();
    if (t < 64) {
        float a = 0.f;
        #pragma unroll
        for (int k = 0; k < KK; k++) a += nbs[k * 64 + t];
        t2s[t] = a;
    }
    __syncthreads();

    // --- xa2s: one (ai,b) pair per thread ---
    {
        int ai = t >> 4, b = t & 15;
        float sgv[4], ctr[4];
        float den = 1e-7f;
        #pragma unroll
        for (int cc = 0; cc < 4; cc++) {
            float raw = x1s[cc * 16 + ai] * t2s[cc * 16 + b]
                      + x1s[cc * 16 + b]  * t2s[cc * 16 + ai];
            float mag = sqrtf(fmaxf(fabsf(raw), 1e-8f));
            float sg  = (raw > 0.f) ? mag : ((raw < 0.f) ? -mag : 0.f);
            sgv[cc] = sg;
            den += fabsf(sg);
        }
        float inv = 1.f / den;
        #pragma unroll
        for (int cc = 0; cc < 4; cc++)
            ctr[cc] = sgv[cc] * inv * x1s[cc * 16 + b];
        #pragma unroll
        for (int d = 8; d > 0; d >>= 1) {
            #pragma unroll
            for (int cc = 0; cc < 4; cc++)
                ctr[cc] += __shfl_down_sync(0xffffffffu, ctr[cc], d, 16);
        }
        if (b == 0) {
            #pragma unroll
            for (int cc = 0; cc < 4; cc++) xa2s[cc * 16 + ai] = ctr[cc];
        }
    }
    __syncthreads();

    // --- W2 matvec: 8 MACs/thread + width-8 reduce ---
    {
        int o = t >> 3, seg = t & 7;
        float acc = 0.f;
        #pragma unroll
        for (int i = seg * 8; i < seg * 8 + 8; i++)
            acc += W2[o * 64 + i] * xa2s[i];
        #pragma unroll
        for (int d = 4; d > 0; d >>= 1)
            acc += __shfl_down_sync(0xffffffffu, acc, d, 8);
        if (seg == 0) g_X2[n * C2c + o] = acc;
    }

    // --- last CTA: BN2 + softsign + linear ---
    __threadfence();
    __syncthreads();
    if (t == 0) last = (atomicAdd(&g_cnt2[0], 1) == NN - 1);
    __syncthreads();
    if (!last) return;
    __threadfence();

    float* z = nbs;                           // reuse 2048-float buffer
    for (int i = t; i < NN * C2c; i += 256) z[i] = g_X2[i];
    __syncthreads();

    // per-q stats over 64 nodes: thread t: q = t&31, group g = t>>5 (8 nodes each)
    {
        int q = t & 31, g = t >> 5;
        float s1 = 0.f, s2 = 0.f;
        #pragma unroll
        for (int nn = g * 8; nn < g * 8 + 8; nn++) {
            float v = z[nn * C2c + q];
            s1 += v; s2 += v * v;
        }
        red[q * 8 + g] = s1; red[256 + q * 8 + g] = s2;
    }
    __syncthreads();
    #pragma unroll
    for (int st = 4; st > 0; st >>= 1) {
        if ((t & 7) < st && t < 256) {
            red[t] += red[t + st];
            red[256 + t] += red[256 + t + st];
        }
        __syncthreads();
    }
    __shared__ float qm[C2c], qr[C2c];
    if (t < C2c) {
        float m = red[t * 8] / 64.f;
        qm[t] = m; qr[t] = rsqrtf(red[256 + t * 8] / 64.f - m * m + BN_EPS);
    }
    __syncthreads();
    for (int i = t; i < NN * C2c; i += 256) {
        int q = i & 31;
        float y = (z[i] - qm[q]) * qr[q] * bn2w[q] + bn2b[q];
        z[i] = y / (1.f + fabsf(y));
    }
    __syncthreads();
    for (int i = t; i < NN * NCLS; i += 256) {
        int nn = i / NCLS, cls = i - nn * NCLS;
        float acc = lb[cls];
        #pragma unroll
        for (int q = 0; q < C2c; q++) acc += z[nn * C2c + q] * lw[cls * C2c + q];
        out[i] = acc;
    }
}

// ============================================================================
extern "C" void kernel_launch(void* const* d_in, const int* in_sizes, int n_in,
                              void* d_out, int out_size)
{
    const float* x    = (const float*)d_in[0];
    const float* nb   = (const float*)d_in[1];
    const float* W1   = (const float*)d_in[2];
    const float* W2   = (const float*)d_in[3];
    const float* bn1w = (const float*)d_in[4];
    const float* bn1b = (const float*)d_in[5];
    const float* bn2w = (const float*)d_in[6];
    const float* bn2b = (const float*)d_in[7];
    const float* lw   = (const float*)d_in[8];
    const float* lb   = (const float*)d_in[9];
    float* out = (float*)d_out;

    k_sort<<<NN, 1024>>>(x, nb);
    dim3 gc(JJ, NN);
    k_cols<<<gc, 1024>>>(x, nb);
    dim3 gg(33, 8);
    k_gemm<<<gg, 256>>>(W1);
    k_layer2<<<NN, 256>>>(W2, bn1w, bn1b, bn2w, bn2b, lw, lb, out);
}